// round 11
// baseline (speedup 1.0000x reference)
#include <cuda_runtime.h>
#include <math.h>

#define NN 100000
#define EE 1200000
#define HIDD 64
#define HH 4
#define DD 16
#define LLAY 3

// ---- scratch (device globals: no allocation allowed) ----
__device__ float g_h[NN * HIDD];     // node features
__device__ float g_hw[NN * HIDD];    // h @ w_gat[l]  (also encoder temp)
__device__ float g_agg[NN * HIDD];   // aggregated messages
__device__ float g_as[NN * HH];
__device__ float g_ad[NN * HH];
__device__ float g_smax[NN * HH];
__device__ float g_den[NN * HH];
__device__ float g_sc[EE * HH];      // score, then exp(score-max)
__device__ float g_coef[LLAY * HH * 2]; // A1, A0 per (layer, head)
__device__ int   g_src[EE];
__device__ int   g_dst[EE];
__device__ int   g_is64;

// ---------------------------------------------------------------------------
__device__ __forceinline__ void atomicMaxFloat(float* addr, float val) {
    int* ia = (int*)addr;
    int old = *ia;
    while (__int_as_float(old) < val) {
        int assumed = old;
        old = atomicCAS(ia, assumed, __float_as_int(val));
        if (old == assumed) break;
    }
}

// ---- diagnostic sentinel: zero-fill output ----
__global__ void fill_zero_kernel(float* o, int n) {
    int i = blockIdx.x * blockDim.x + threadIdx.x;
    if (i < n) o[i] = 0.0f;
}

// ---- edge_index dtype detection + normalization ----
__global__ void detect_kernel(const void* ei) {
    const long long* p = (const long long*)ei;
    int ok = 1;
    for (int i = 0; i < 256; i++) {
        long long v = p[i];
        if (v < 0 || v >= NN) { ok = 0; break; }
    }
    g_is64 = ok;
}

__global__ void convert_kernel(const void* ei) {
    int i = blockIdx.x * blockDim.x + threadIdx.x;
    if (i >= EE) return;
    if (g_is64) {
        const long long* p = (const long long*)ei;
        g_src[i] = (int)p[i];
        g_dst[i] = (int)p[EE + i];
    } else {
        const int* p = (const int*)ei;
        g_src[i] = p[i];
        g_dst[i] = p[EE + i];
    }
}

// ---- generic small GEMM: C[n,64] = act(A[n,K] @ W[K,64] + b) ----
// blockDim = 256 (4 rows x 64 cols per block).
// NOTE: A and C must be REAL device addresses (cudaGetSymbolAddress for
// __device__ globals) — passing a __device__ symbol from host silently
// passes the host shadow address (ATS makes it "work" on GB300 = R7-9 bug).
template <int K, int ACT, int HASB>
__global__ void gemm_kernel(const float* __restrict__ A,
                            const float* __restrict__ W,
                            const float* __restrict__ b,
                            float* __restrict__ C, int n) {
    __shared__ float sW[K * 64];
    __shared__ float sb[64];
    int tid = threadIdx.x;
    for (int i = tid; i < K * 64; i += 256) sW[i] = W[i];
    if (HASB && tid < 64) sb[tid] = b[tid];
    __syncthreads();

    int row = blockIdx.x * 4 + (tid >> 6);
    int c = tid & 63;
    if (row >= n) return;
    const float* a = A + (size_t)row * K;
    float acc = HASB ? sb[c] : 0.0f;
#pragma unroll
    for (int k = 0; k < K; k++) acc = fmaf(__ldg(a + k), sW[k * 64 + c], acc);
    if (ACT) acc = fmaxf(acc, 0.0f);
    C[(size_t)row * 64 + c] = acc;
}

// ---- edge-feature attention coefficients (rank-1 collapse of edge path) ----
// a_e[j,h] = ea[j]*A1[l,h] + A0[l,h]
__global__ void ecoef_kernel(const float* __restrict__ w_ee,
                             const float* __restrict__ b_ee,
                             const float* __restrict__ w_eg,
                             const float* __restrict__ att_edge) {
    int idx = threadIdx.x;
    if (idx >= LLAY * HH) return;
    int l = idx / HH, h = idx % HH;
    float c1 = 0.f, c0 = 0.f;
    for (int d = 0; d < DD; d++) {
        int col = h * DD + d;
        float t1 = 0.f, t0 = 0.f;
        for (int k = 0; k < HIDD; k++) {
            float w = w_eg[((size_t)l * HIDD + k) * HIDD + col];
            t1 += w_ee[k] * w;
            t0 += b_ee[k] * w;
        }
        float a = att_edge[((size_t)l * HH + h) * DD + d];
        c1 = fmaf(t1, a, c1);
        c0 = fmaf(t0, a, c0);
    }
    g_coef[idx * 2] = c1;
    g_coef[idx * 2 + 1] = c0;
}

// ---- per-node attention logits a_s, a_d ----
__global__ void asd_kernel(const float* __restrict__ att_src,
                           const float* __restrict__ att_dst) {
    int idx = blockIdx.x * blockDim.x + threadIdx.x;
    if (idx >= NN * HH) return;
    int node = idx >> 2, h = idx & 3;
    const float* v = g_hw + (size_t)node * HIDD + h * DD;
    float s = 0.f, d = 0.f;
#pragma unroll
    for (int k = 0; k < DD; k++) {
        float x = v[k];
        s = fmaf(x, att_src[h * DD + k], s);
        d = fmaf(x, att_dst[h * DD + k], d);
    }
    g_as[idx] = s;
    g_ad[idx] = d;
}

// ---- zero/init per layer: agg=0, smax=-FLT_MAX, den=0 ----
__global__ void init_kernel() {
    int idx = blockIdx.x * blockDim.x + threadIdx.x;
    if (idx < NN * HIDD) {
        g_agg[idx] = 0.f;
    } else if (idx < NN * HIDD + NN * HH) {
        g_smax[idx - NN * HIDD] = -3.4e38f;
    } else if (idx < NN * HIDD + 2 * NN * HH) {
        g_den[idx - NN * HIDD - NN * HH] = 0.f;
    }
}

// ---- edge pass 1: score + segment max ----
__global__ void edge1_kernel(const float* __restrict__ ea, int layer) {
    int idx = blockIdx.x * blockDim.x + threadIdx.x;
    if (idx >= EE * HH) return;
    int j = idx >> 2, h = idx & 3;
    int s = g_src[j], d = g_dst[j];
    float c1 = g_coef[(layer * HH + h) * 2];
    float c0 = g_coef[(layer * HH + h) * 2 + 1];
    float v = g_as[s * HH + h] + g_ad[d * HH + h] + fmaf(__ldg(ea + j), c1, c0);
    v = (v > 0.f) ? v : 0.2f * v;   // leaky_relu(0.2)
    g_sc[idx] = v;
    atomicMaxFloat(&g_smax[d * HH + h], v);
}

// ---- edge pass 2: exp + segment sum ----
__global__ void edge2_kernel() {
    int idx = blockIdx.x * blockDim.x + threadIdx.x;
    if (idx >= EE * HH) return;
    int j = idx >> 2, h = idx & 3;
    int d = g_dst[j];
    float ex = expf(g_sc[idx] - g_smax[d * HH + h]);
    g_sc[idx] = ex;
    atomicAdd(&g_den[d * HH + h], ex);
}

// ---- edge pass 3: weighted scatter of messages ----
__global__ void edge3_kernel() {
    long long idx = (long long)blockIdx.x * blockDim.x + threadIdx.x;
    if (idx >= (long long)EE * HIDD) return;
    int j = (int)(idx >> 6);
    int c = (int)(idx & 63);
    int h = c >> 4;
    int s = g_src[j], d = g_dst[j];
    float alpha = g_sc[j * HH + h] / (g_den[d * HH + h] + 1e-16f);
    atomicAdd(&g_agg[(size_t)d * HIDD + c], alpha * g_hw[(size_t)s * HIDD + c]);
}

// ---- node update: h = layernorm(h + elu(agg + b_gat)) ----
__global__ void node_update_kernel(const float* __restrict__ b_gat,
                                   const float* __restrict__ ln_g,
                                   const float* __restrict__ ln_b) {
    int tid = threadIdx.x;
    int node = blockIdx.x * 4 + (tid >> 6);
    int c = tid & 63;

    float a = g_agg[(size_t)node * HIDD + c] + b_gat[c];
    float el = (a > 0.f) ? a : (expf(a) - 1.0f);
    float v = g_h[(size_t)node * HIDD + c] + el;

    float sum = v, sq = v * v;
#pragma unroll
    for (int o = 16; o; o >>= 1) {
        sum += __shfl_xor_sync(0xffffffff, sum, o);
        sq += __shfl_xor_sync(0xffffffff, sq, o);
    }
    __shared__ float ssum[8], ssq[8];
    int warpid = tid >> 5;
    if ((tid & 31) == 0) { ssum[warpid] = sum; ssq[warpid] = sq; }
    __syncthreads();
    int g = tid >> 6;
    float tot = ssum[g * 2] + ssum[g * 2 + 1];
    float totsq = ssq[g * 2] + ssq[g * 2 + 1];
    float mean = tot * (1.0f / 64.0f);
    float var = totsq * (1.0f / 64.0f) - mean * mean;
    float out = (v - mean) * rsqrtf(var + 1e-5f) * ln_g[c] + ln_b[c];
    g_h[(size_t)node * HIDD + c] = out;
}

// ---------------------------------------------------------------------------
// Logical input ids (reference-signature order):
enum { I_X, I_EI, I_EA, I_WNE1, I_BNE1, I_WNE2, I_BNE2, I_WEE, I_BEE,
       I_WGAT, I_WEG, I_ASRC, I_ADST, I_AEDGE, I_BGAT, I_LNG, I_LNB,
       I_WOUT, I_BOUT, I_COUNT };

extern "C" void kernel_launch(void* const* d_in, const int* in_sizes, int n_in,
                              void* d_out, int out_size) {
    float* out = (float*)d_out;

    // Expected ELEMENT counts in reference-signature order.
    static const long long EXP_ELEM[19] = {
        600000, 2400000, 1200000, 384, 64, 4096, 64, 64, 64,
        12288, 12288, 192, 192, 192, 192, 192, 192, 4096, 64};

    // ---- robust size-driven binding (elements / bytes-int32 / bytes-int64)
    int perm[19];
    bool resolved = false;
    if (n_in == 19) {
        for (int u = 0; u < 3 && !resolved; u++) {
            long long want[19];
            for (int i = 0; i < 19; i++)
                want[i] = EXP_ELEM[i] * (u == 0 ? 1LL : 4LL);
            if (u == 2) want[1] = EXP_ELEM[1] * 8LL;
            bool used[19] = {false};
            bool good = true;
            for (int i = 0; i < 19 && good; i++) {
                int found = -1;
                for (int j = 0; j < 19; j++) {
                    if (!used[j] && (long long)in_sizes[j] == want[i]) {
                        found = j;
                        break;
                    }
                }
                if (found < 0) { good = false; break; }
                perm[i] = found;
                used[found] = true;
            }
            if (good) resolved = true;
        }
    }

    if (!resolved) {
        fill_zero_kernel<<<(out_size + 255) / 256, 256>>>(out, out_size);
        return;
    }

    const float* x        = (const float*)d_in[perm[I_X]];
    const void*  ei       = d_in[perm[I_EI]];
    const float* ea       = (const float*)d_in[perm[I_EA]];
    const float* w_ne1    = (const float*)d_in[perm[I_WNE1]];
    const float* b_ne1    = (const float*)d_in[perm[I_BNE1]];
    const float* w_ne2    = (const float*)d_in[perm[I_WNE2]];
    const float* b_ne2    = (const float*)d_in[perm[I_BNE2]];
    const float* w_ee     = (const float*)d_in[perm[I_WEE]];
    const float* b_ee     = (const float*)d_in[perm[I_BEE]];
    const float* w_gat    = (const float*)d_in[perm[I_WGAT]];
    const float* w_eg     = (const float*)d_in[perm[I_WEG]];
    const float* att_src  = (const float*)d_in[perm[I_ASRC]];
    const float* att_dst  = (const float*)d_in[perm[I_ADST]];
    const float* att_edge = (const float*)d_in[perm[I_AEDGE]];
    const float* b_gat    = (const float*)d_in[perm[I_BGAT]];
    const float* ln_g     = (const float*)d_in[perm[I_LNG]];
    const float* ln_b     = (const float*)d_in[perm[I_LNB]];
    const float* w_out    = (const float*)d_in[perm[I_WOUT]];
    const float* b_out    = (const float*)d_in[perm[I_BOUT]];

    // *** THE FIX ***: real device addresses of the __device__ globals.
    // Referencing g_h/g_hw directly in host code passes the HOST shadow
    // address; GB300's ATS dereferences it "successfully" over NVLink-C2C,
    // silently splitting the pipeline between host and device copies.
    float *p_h = nullptr, *p_hw = nullptr;
    cudaGetSymbolAddress((void**)&p_h, g_h);
    cudaGetSymbolAddress((void**)&p_hw, g_hw);

    // edge index normalization (int64 vs int32 robust)
    detect_kernel<<<1, 1>>>(ei);
    convert_kernel<<<(EE + 255) / 256, 256>>>(ei);

    // node encoder: hw = relu(x@w_ne1+b1); h = hw@w_ne2+b2
    gemm_kernel<6, 1, 1><<<NN / 4, 256>>>(x, w_ne1, b_ne1, p_hw, NN);
    gemm_kernel<64, 0, 1><<<NN / 4, 256>>>(p_hw, w_ne2, b_ne2, p_h, NN);

    // edge-path attention coefficients (rank-1 collapse)
    ecoef_kernel<<<1, 32>>>(w_ee, b_ee, w_eg, att_edge);

    for (int l = 0; l < LLAY; l++) {
        gemm_kernel<64, 0, 0><<<NN / 4, 256>>>(p_h, w_gat + (size_t)l * 64 * 64,
                                               nullptr, p_hw, NN);
        asd_kernel<<<(NN * HH + 255) / 256, 256>>>(att_src + l * HH * DD,
                                                   att_dst + l * HH * DD);
        init_kernel<<<(NN * (HIDD + 2 * HH) + 255) / 256, 256>>>();
        edge1_kernel<<<(EE * HH + 255) / 256, 256>>>(ea, l);
        edge2_kernel<<<(EE * HH + 255) / 256, 256>>>();
        {
            long long tot = (long long)EE * HIDD;
            int blocks = (int)((tot + 255) / 256);
            edge3_kernel<<<blocks, 256>>>();
        }
        node_update_kernel<<<NN / 4, 256>>>(b_gat + l * HIDD, ln_g + l * HIDD,
                                            ln_b + l * HIDD);
    }

    // output projection
    gemm_kernel<64, 0, 1><<<NN / 4, 256>>>(p_h, w_out, b_out, out, NN);
}

// round 12
// speedup vs baseline: 2.7104x; 2.7104x over previous
#include <cuda_runtime.h>
#include <math.h>

#define NN 100000
#define EE 1200000
#define HIDD 64
#define HH 4
#define DD 16
#define LLAY 3
#define NBLK_SCAN 391   // ceil(NN/256)

// ---- scratch (device globals; 16B-aligned for float4 access) ----
__device__ __align__(16) float g_h[NN * HIDD];
__device__ __align__(16) float g_hw[NN * HIDD];
__device__ __align__(16) float g_as[NN * HH];
__device__ __align__(16) float g_ad[NN * HH];
__device__ __align__(16) float g_sc[EE * HH];        // scores, CSR order
__device__ __align__(16) float g_coef[LLAY * HH * 2];
__device__ int g_src[EE];
__device__ int g_dst[EE];
__device__ int g_deg[NN];
__device__ int g_off[NN + 1];
__device__ int g_pos[NN];
__device__ int g_eid[EE];       // edge ids sorted by dst (CSR)
__device__ int g_bsum[NBLK_SCAN];
__device__ int g_bpre[NBLK_SCAN];
__device__ int g_is64;

// ---- diagnostic sentinel ----
__global__ void fill_zero_kernel(float* o, int n) {
    int i = blockIdx.x * blockDim.x + threadIdx.x;
    if (i < n) o[i] = 0.0f;
}

// ---- edge_index dtype detection + normalization ----
__global__ void detect_kernel(const void* ei) {
    const long long* p = (const long long*)ei;
    int ok = 1;
    for (int i = 0; i < 256; i++) {
        long long v = p[i];
        if (v < 0 || v >= NN) { ok = 0; break; }
    }
    g_is64 = ok;
}

__global__ void convert_kernel(const void* ei) {
    int i = blockIdx.x * blockDim.x + threadIdx.x;
    if (i >= EE) return;
    if (g_is64) {
        const long long* p = (const long long*)ei;
        g_src[i] = (int)p[i];
        g_dst[i] = (int)p[EE + i];
    } else {
        const int* p = (const int*)ei;
        g_src[i] = p[i];
        g_dst[i] = p[EE + i];
    }
}

// ---- CSR build: histogram + 3-step scan + fill ----
__global__ void zero_deg_kernel() {
    int i = blockIdx.x * blockDim.x + threadIdx.x;
    if (i < NN) g_deg[i] = 0;
}

__global__ void hist_kernel() {
    int e = blockIdx.x * blockDim.x + threadIdx.x;
    if (e < EE) atomicAdd(&g_deg[g_dst[e]], 1);
}

__global__ void scan1_kernel() {   // per-block sums
    __shared__ int s[256];
    int i = blockIdx.x * 256 + threadIdx.x;
    s[threadIdx.x] = (i < NN) ? g_deg[i] : 0;
    __syncthreads();
    for (int o = 128; o; o >>= 1) {
        if (threadIdx.x < o) s[threadIdx.x] += s[threadIdx.x + o];
        __syncthreads();
    }
    if (threadIdx.x == 0) g_bsum[blockIdx.x] = s[0];
}

__global__ void scan2_kernel() {   // scan of block sums (one 512-thread block)
    __shared__ int s[512];
    int tid = threadIdx.x;
    int v = (tid < NBLK_SCAN) ? g_bsum[tid] : 0;
    s[tid] = v;
    __syncthreads();
    for (int o = 1; o < 512; o <<= 1) {
        int t = (tid >= o) ? s[tid - o] : 0;
        __syncthreads();
        s[tid] += t;
        __syncthreads();
    }
    if (tid < NBLK_SCAN) g_bpre[tid] = s[tid] - v;   // exclusive
    if (tid == 0) g_off[NN] = EE;
}

__global__ void scan3_kernel() {   // per-element exclusive offsets
    __shared__ int s[256];
    int tid = threadIdx.x;
    int i = blockIdx.x * 256 + tid;
    int v = (i < NN) ? g_deg[i] : 0;
    s[tid] = v;
    __syncthreads();
    for (int o = 1; o < 256; o <<= 1) {
        int t = (tid >= o) ? s[tid - o] : 0;
        __syncthreads();
        s[tid] += t;
        __syncthreads();
    }
    if (i < NN) {
        int ex = s[tid] - v + g_bpre[blockIdx.x];
        g_off[i] = ex;
        g_pos[i] = ex;
    }
}

__global__ void fill_kernel() {
    int e = blockIdx.x * blockDim.x + threadIdx.x;
    if (e >= EE) return;
    int d = g_dst[e];
    int slot = atomicAdd(&g_pos[d], 1);
    g_eid[slot] = e;
}

// ---- GEMM: C[n,64] = act(A[n,K] @ W[K,64] + b), 16 rows x 16 thr x 4 cols ----
// FATT=1 additionally computes a_s/a_d dot products from the fresh accumulator.
template <int K, int ACT, int HASB, int FATT>
__global__ void gemm64_kernel(const float* __restrict__ A,
                              const float* __restrict__ W,
                              const float* __restrict__ b,
                              float* __restrict__ C,
                              const float* __restrict__ att_s,
                              const float* __restrict__ att_d, int n) {
    __shared__ float4 sW[K * 16];
    __shared__ float sA[16 * (K + 1)];
    __shared__ float4 sAS[16], sAD[16], sb4[16];
    int tid = threadIdx.x;
    for (int i = tid; i < K * 16; i += 256) sW[i] = ((const float4*)W)[i];
    if (HASB && tid < 16) sb4[tid] = ((const float4*)b)[tid];
    if (FATT && tid < 16) {
        sAS[tid] = ((const float4*)att_s)[tid];
        sAD[tid] = ((const float4*)att_d)[tid];
    }
    int row0 = blockIdx.x * 16;
    for (int i = tid; i < 16 * K; i += 256) {
        int r = i / K, k = i % K;
        sA[r * (K + 1) + k] = A[(size_t)(row0 + r) * K + k];
    }
    __syncthreads();

    int r = tid >> 4, cg = tid & 15;
    int row = row0 + r;
    if (row >= n) return;   // never fires for n%16==0 grids used here
    float4 acc = HASB ? sb4[cg] : make_float4(0.f, 0.f, 0.f, 0.f);
    const float* a = &sA[r * (K + 1)];
#pragma unroll
    for (int k = 0; k < K; k++) {
        float av = a[k];
        float4 w = sW[k * 16 + cg];
        acc.x = fmaf(av, w.x, acc.x);
        acc.y = fmaf(av, w.y, acc.y);
        acc.z = fmaf(av, w.z, acc.z);
        acc.w = fmaf(av, w.w, acc.w);
    }
    if (ACT) {
        acc.x = fmaxf(acc.x, 0.f); acc.y = fmaxf(acc.y, 0.f);
        acc.z = fmaxf(acc.z, 0.f); acc.w = fmaxf(acc.w, 0.f);
    }
    ((float4*)C)[(size_t)row * 16 + cg] = acc;

    if (FATT) {
        float4 s4 = sAS[cg], d4 = sAD[cg];
        float ps = acc.x * s4.x + acc.y * s4.y + acc.z * s4.z + acc.w * s4.w;
        float pd = acc.x * d4.x + acc.y * d4.y + acc.z * d4.z + acc.w * d4.w;
        ps += __shfl_xor_sync(0xffffffffu, ps, 1);
        ps += __shfl_xor_sync(0xffffffffu, ps, 2);
        pd += __shfl_xor_sync(0xffffffffu, pd, 1);
        pd += __shfl_xor_sync(0xffffffffu, pd, 2);
        if ((cg & 3) == 0) {
            int head = cg >> 2;
            g_as[row * 4 + head] = ps;
            g_ad[row * 4 + head] = pd;
        }
    }
}

// ---- edge-feature attention coefficients (rank-1 collapse) ----
__global__ void ecoef_kernel(const float* __restrict__ w_ee,
                             const float* __restrict__ b_ee,
                             const float* __restrict__ w_eg,
                             const float* __restrict__ att_edge) {
    int idx = threadIdx.x;
    if (idx >= LLAY * HH) return;
    int l = idx / HH, h = idx % HH;
    float c1 = 0.f, c0 = 0.f;
    for (int d = 0; d < DD; d++) {
        int col = h * DD + d;
        float t1 = 0.f, t0 = 0.f;
        for (int k = 0; k < HIDD; k++) {
            float w = w_eg[((size_t)l * HIDD + k) * HIDD + col];
            t1 += w_ee[k] * w;
            t0 += b_ee[k] * w;
        }
        float a = att_edge[((size_t)l * HH + h) * DD + d];
        c1 = fmaf(t1, a, c1);
        c0 = fmaf(t0, a, c0);
    }
    g_coef[idx * 2] = c1;
    g_coef[idx * 2 + 1] = c0;
}

// ---- fused GAT layer: warp per dst node ----
// score -> segment max -> exp/den -> weighted gather -> +bias,ELU,residual,LN
__global__ void gat_kernel(const float* __restrict__ ea, int layer,
                           const float* __restrict__ b_gat,
                           const float* __restrict__ ln_g,
                           const float* __restrict__ ln_b) {
    int n = (blockIdx.x * blockDim.x + threadIdx.x) >> 5;
    int lane = threadIdx.x & 31;
    if (n >= NN) return;
    int off = g_off[n];
    int deg = g_off[n + 1] - off;

    // coefs: g_coef layout [l][h][2] -> 8 floats per layer = 2 float4s
    float4 cA = ((const float4*)g_coef)[layer * 2];      // h0.c1,h0.c0,h1.c1,h1.c0
    float4 cB = ((const float4*)g_coef)[layer * 2 + 1];  // h2,h3
    float4 ad4 = ((const float4*)g_ad)[n];

    // pass A: scores + per-head max
    float mx0 = -3.4e38f, mx1 = mx0, mx2 = mx0, mx3 = mx0;
    for (int i = lane; i < deg; i += 32) {
        int e = g_eid[off + i];
        int s = g_src[e];
        float ev = __ldg(ea + e);
        float4 as4 = ((const float4*)g_as)[s];
        float s0 = as4.x + ad4.x + fmaf(ev, cA.x, cA.y);
        float s1 = as4.y + ad4.y + fmaf(ev, cA.z, cA.w);
        float s2 = as4.z + ad4.z + fmaf(ev, cB.x, cB.y);
        float s3 = as4.w + ad4.w + fmaf(ev, cB.z, cB.w);
        s0 = (s0 > 0.f) ? s0 : 0.2f * s0;
        s1 = (s1 > 0.f) ? s1 : 0.2f * s1;
        s2 = (s2 > 0.f) ? s2 : 0.2f * s2;
        s3 = (s3 > 0.f) ? s3 : 0.2f * s3;
        ((float4*)g_sc)[off + i] = make_float4(s0, s1, s2, s3);
        mx0 = fmaxf(mx0, s0); mx1 = fmaxf(mx1, s1);
        mx2 = fmaxf(mx2, s2); mx3 = fmaxf(mx3, s3);
    }
#pragma unroll
    for (int o = 16; o; o >>= 1) {
        mx0 = fmaxf(mx0, __shfl_xor_sync(0xffffffffu, mx0, o));
        mx1 = fmaxf(mx1, __shfl_xor_sync(0xffffffffu, mx1, o));
        mx2 = fmaxf(mx2, __shfl_xor_sync(0xffffffffu, mx2, o));
        mx3 = fmaxf(mx3, __shfl_xor_sync(0xffffffffu, mx3, o));
    }

    // pass B: exp + den
    float d0 = 0.f, d1 = 0.f, d2 = 0.f, d3 = 0.f;
    for (int i = lane; i < deg; i += 32) {
        float4 sc = ((const float4*)g_sc)[off + i];
        float e0 = __expf(sc.x - mx0);
        float e1 = __expf(sc.y - mx1);
        float e2 = __expf(sc.z - mx2);
        float e3 = __expf(sc.w - mx3);
        ((float4*)g_sc)[off + i] = make_float4(e0, e1, e2, e3);
        d0 += e0; d1 += e1; d2 += e2; d3 += e3;
    }
#pragma unroll
    for (int o = 16; o; o >>= 1) {
        d0 += __shfl_xor_sync(0xffffffffu, d0, o);
        d1 += __shfl_xor_sync(0xffffffffu, d1, o);
        d2 += __shfl_xor_sync(0xffffffffu, d2, o);
        d3 += __shfl_xor_sync(0xffffffffu, d3, o);
    }
    float i0 = 1.f / (d0 + 1e-16f), i1 = 1.f / (d1 + 1e-16f);
    float i2 = 1.f / (d2 + 1e-16f), i3 = 1.f / (d3 + 1e-16f);

    __syncwarp();   // pass-B global writes visible to all lanes before pass C

    // pass C: serial over edges, lanes over 64 cols (lane, lane+32)
    bool hi = (lane >= 16);
    float invA = hi ? i1 : i0;    // col = lane       -> head lane/16
    float invB = hi ? i3 : i2;    // col = lane + 32  -> head 2 + lane/16
    float acc0 = 0.f, acc1 = 0.f;
    for (int i = 0; i < deg; i++) {
        int e = g_eid[off + i];               // warp-broadcast load
        int s = g_src[e];
        float4 ex = ((const float4*)g_sc)[off + i];
        float aA = (hi ? ex.y : ex.x) * invA;
        float aB = (hi ? ex.w : ex.z) * invB;
        const float* hwrow = &g_hw[(size_t)s * 64];
        acc0 = fmaf(aA, hwrow[lane], acc0);
        acc1 = fmaf(aB, hwrow[lane + 32], acc1);
    }

    // fused node update: +bias, ELU, residual, LayerNorm
    float a0 = acc0 + __ldg(b_gat + lane);
    float a1 = acc1 + __ldg(b_gat + lane + 32);
    float e0 = (a0 > 0.f) ? a0 : (expf(a0) - 1.f);
    float e1 = (a1 > 0.f) ? a1 : (expf(a1) - 1.f);
    float v0 = g_h[(size_t)n * 64 + lane] + e0;
    float v1 = g_h[(size_t)n * 64 + 32 + lane] + e1;
    float sum = v0 + v1, sq = v0 * v0 + v1 * v1;
#pragma unroll
    for (int o = 16; o; o >>= 1) {
        sum += __shfl_xor_sync(0xffffffffu, sum, o);
        sq += __shfl_xor_sync(0xffffffffu, sq, o);
    }
    float mean = sum * (1.0f / 64.0f);
    float var = sq * (1.0f / 64.0f) - mean * mean;
    float rstd = rsqrtf(var + 1e-5f);
    g_h[(size_t)n * 64 + lane] =
        (v0 - mean) * rstd * __ldg(ln_g + lane) + __ldg(ln_b + lane);
    g_h[(size_t)n * 64 + 32 + lane] =
        (v1 - mean) * rstd * __ldg(ln_g + lane + 32) + __ldg(ln_b + lane + 32);
}

// ---------------------------------------------------------------------------
enum { I_X, I_EI, I_EA, I_WNE1, I_BNE1, I_WNE2, I_BNE2, I_WEE, I_BEE,
       I_WGAT, I_WEG, I_ASRC, I_ADST, I_AEDGE, I_BGAT, I_LNG, I_LNB,
       I_WOUT, I_BOUT, I_COUNT };

extern "C" void kernel_launch(void* const* d_in, const int* in_sizes, int n_in,
                              void* d_out, int out_size) {
    float* out = (float*)d_out;

    static const long long EXP_ELEM[19] = {
        600000, 2400000, 1200000, 384, 64, 4096, 64, 64, 64,
        12288, 12288, 192, 192, 192, 192, 192, 192, 4096, 64};

    int perm[19];
    bool resolved = false;
    if (n_in == 19) {
        for (int u = 0; u < 3 && !resolved; u++) {
            long long want[19];
            for (int i = 0; i < 19; i++)
                want[i] = EXP_ELEM[i] * (u == 0 ? 1LL : 4LL);
            if (u == 2) want[1] = EXP_ELEM[1] * 8LL;
            bool used[19] = {false};
            bool good = true;
            for (int i = 0; i < 19 && good; i++) {
                int found = -1;
                for (int j = 0; j < 19; j++) {
                    if (!used[j] && (long long)in_sizes[j] == want[i]) {
                        found = j;
                        break;
                    }
                }
                if (found < 0) { good = false; break; }
                perm[i] = found;
                used[found] = true;
            }
            if (good) resolved = true;
        }
    }
    if (!resolved) {
        fill_zero_kernel<<<(out_size + 255) / 256, 256>>>(out, out_size);
        return;
    }

    const float* x        = (const float*)d_in[perm[I_X]];
    const void*  ei       = d_in[perm[I_EI]];
    const float* ea       = (const float*)d_in[perm[I_EA]];
    const float* w_ne1    = (const float*)d_in[perm[I_WNE1]];
    const float* b_ne1    = (const float*)d_in[perm[I_BNE1]];
    const float* w_ne2    = (const float*)d_in[perm[I_WNE2]];
    const float* b_ne2    = (const float*)d_in[perm[I_BNE2]];
    const float* w_ee     = (const float*)d_in[perm[I_WEE]];
    const float* b_ee     = (const float*)d_in[perm[I_BEE]];
    const float* w_gat    = (const float*)d_in[perm[I_WGAT]];
    const float* w_eg     = (const float*)d_in[perm[I_WEG]];
    const float* att_src  = (const float*)d_in[perm[I_ASRC]];
    const float* att_dst  = (const float*)d_in[perm[I_ADST]];
    const float* att_edge = (const float*)d_in[perm[I_AEDGE]];
    const float* b_gat    = (const float*)d_in[perm[I_BGAT]];
    const float* ln_g     = (const float*)d_in[perm[I_LNG]];
    const float* ln_b     = (const float*)d_in[perm[I_LNB]];
    const float* w_out    = (const float*)d_in[perm[I_WOUT]];
    const float* b_out    = (const float*)d_in[perm[I_BOUT]];

    // REAL device addresses of __device__ globals (R11 fix: host-shadow + ATS)
    float *p_h = nullptr, *p_hw = nullptr;
    cudaGetSymbolAddress((void**)&p_h, g_h);
    cudaGetSymbolAddress((void**)&p_hw, g_hw);

    const int EB = (EE + 255) / 256;

    // edge index normalization + CSR build (by dst)
    detect_kernel<<<1, 1>>>(ei);
    convert_kernel<<<EB, 256>>>(ei);
    zero_deg_kernel<<<NBLK_SCAN, 256>>>();
    hist_kernel<<<EB, 256>>>();
    scan1_kernel<<<NBLK_SCAN, 256>>>();
    scan2_kernel<<<1, 512>>>();
    scan3_kernel<<<NBLK_SCAN, 256>>>();
    fill_kernel<<<EB, 256>>>();

    // node encoder
    gemm64_kernel<6, 1, 1, 0><<<NN / 16, 256>>>(x, w_ne1, b_ne1, p_hw,
                                                nullptr, nullptr, NN);
    gemm64_kernel<64, 0, 1, 0><<<NN / 16, 256>>>(p_hw, w_ne2, b_ne2, p_h,
                                                 nullptr, nullptr, NN);

    // edge-path attention coefficients (rank-1 collapse)
    ecoef_kernel<<<1, 32>>>(w_ee, b_ee, w_eg, att_edge);

    for (int l = 0; l < LLAY; l++) {
        // hw = h @ w_gat[l], fused a_s/a_d
        gemm64_kernel<64, 0, 0, 1><<<NN / 16, 256>>>(
            p_h, w_gat + (size_t)l * 64 * 64, nullptr, p_hw,
            att_src + l * 64, att_dst + l * 64, NN);
        // fused softmax + aggregate + node update (warp per node)
        gat_kernel<<<(NN + 7) / 8, 256>>>(ea, l, b_gat + l * HIDD,
                                          ln_g + l * HIDD, ln_b + l * HIDD);
    }

    // output projection
    gemm64_kernel<64, 0, 1, 0><<<NN / 16, 256>>>(p_h, w_out, b_out, out,
                                                 nullptr, nullptr, NN);
}